// round 1
// baseline (speedup 1.0000x reference)
#include <cuda_runtime.h>
#include <math.h>

// Problem constants (fixed by the reference)
#define N_TOK 32768      // B*S
#define DIM   768        // D
#define HID   3072       // H
#define NEXP  8          // E
#define CAP   10240      // int(1.25 * N * K / E)

// ---------------------------------------------------------------------------
// Scratch (device globals: allocation-free per harness rules)
// ---------------------------------------------------------------------------
__device__ int   g_cnt[NEXP];
__device__ int   g_route_e[N_TOK * 2];
__device__ float g_route_w[N_TOK * 2];
__device__ int   g_tokidx[NEXP * CAP];
__device__ int   g_slot[N_TOK * 2];
__device__ float g_H[(size_t)NEXP * CAP * HID];   // ~1.0 GB
__device__ float g_Y[(size_t)NEXP * CAP * DIM];   // ~252 MB

// ---------------------------------------------------------------------------
// Kernel 0: zero the per-expert counters
// ---------------------------------------------------------------------------
__global__ void zero_counts_kernel() {
    if (threadIdx.x < NEXP) g_cnt[threadIdx.x] = 0;
}

// ---------------------------------------------------------------------------
// Kernel 1: router. One warp per token: logits = x @ w_gate, top-2, softmax.
// Tie semantics: strict > keeps the earliest index (matches jax.lax.top_k).
// ---------------------------------------------------------------------------
__global__ __launch_bounds__(256) void router_kernel(
    const float* __restrict__ x, const float* __restrict__ wg)
{
    int warp = (blockIdx.x * blockDim.x + threadIdx.x) >> 5;
    int lane = threadIdx.x & 31;
    if (warp >= N_TOK) return;
    const float* xr = x + (size_t)warp * DIM;

    float acc[NEXP];
#pragma unroll
    for (int e = 0; e < NEXP; e++) acc[e] = 0.f;

    for (int j = lane; j < DIM; j += 32) {
        float xv = xr[j];
        const float* wr = wg + j * NEXP;
#pragma unroll
        for (int e = 0; e < NEXP; e++) acc[e] += xv * wr[e];
    }
#pragma unroll
    for (int e = 0; e < NEXP; e++) {
#pragma unroll
        for (int o = 16; o > 0; o >>= 1)
            acc[e] += __shfl_xor_sync(0xffffffffu, acc[e], o);
    }
    if (lane == 0) {
        int e0 = 0; float v0 = acc[0];
#pragma unroll
        for (int e = 1; e < NEXP; e++) if (acc[e] > v0) { v0 = acc[e]; e0 = e; }
        int e1 = -1; float v1 = -3.4e38f;
#pragma unroll
        for (int e = 0; e < NEXP; e++) if (e != e0 && acc[e] > v1) { v1 = acc[e]; e1 = e; }
        float ex = expf(v1 - v0);
        float s  = 1.f + ex;
        g_route_e[2 * warp + 0] = e0;  g_route_w[2 * warp + 0] = 1.f / s;
        g_route_e[2 * warp + 1] = e1;  g_route_w[2 * warp + 1] = ex / s;
    }
}

// ---------------------------------------------------------------------------
// Kernel 2: expert slot assignment (atomic counters). Order-independent math.
// ---------------------------------------------------------------------------
__global__ void assign_kernel() {
    int t = blockIdx.x * blockDim.x + threadIdx.x;
    if (t >= N_TOK) return;
#pragma unroll
    for (int k = 0; k < 2; k++) {
        int e = g_route_e[2 * t + k];
        int pos = atomicAdd(&g_cnt[e], 1);
        if (pos < CAP) {
            g_tokidx[e * CAP + pos] = t;
            g_slot[2 * t + k] = e * CAP + pos;
        } else {
            g_slot[2 * t + k] = -1;   // cannot trigger for this data distribution
        }
    }
}

// ---------------------------------------------------------------------------
// GEMM1: H = gelu( gather(x) @ w1[e] + b1[e] )   [Me x 768] @ [768 x 3072]
// Tiles: BM=BN=128, BK=8, 256 threads, 8x8 accumulators per thread.
// ---------------------------------------------------------------------------
__global__ __launch_bounds__(256) void gemm1_kernel(
    const float* __restrict__ x,
    const float* __restrict__ w1,
    const float* __restrict__ b1)
{
    const int e  = blockIdx.z;
    const int Me = min(g_cnt[e], CAP);
    const int m0 = blockIdx.y * 128;
    if (m0 >= Me) return;
    const int n0 = blockIdx.x * 128;

    __shared__ float As[8][128];
    __shared__ float Bs[8][128];

    const int tid  = threadIdx.x;
    const int a_rm = tid >> 1;
    const int a_c4 = (tid & 1) * 4;
    int tokA = -1;
    if (m0 + a_rm < Me) tokA = g_tokidx[e * CAP + m0 + a_rm];

    const int b_kk = tid >> 5;          // 0..7
    const int b_n  = (tid & 31) * 4;    // 0..124
    const float* Bbase = w1 + (size_t)e * DIM * HID + n0 + b_n;

    const int ty = tid >> 4, tx = tid & 15;

    float acc[8][8];
#pragma unroll
    for (int i = 0; i < 8; i++)
#pragma unroll
        for (int j = 0; j < 8; j++) acc[i][j] = 0.f;

    for (int k0 = 0; k0 < DIM; k0 += 8) {
        float4 av = make_float4(0.f, 0.f, 0.f, 0.f);
        if (tokA >= 0)
            av = *(const float4*)(x + (size_t)tokA * DIM + k0 + a_c4);
        As[a_c4 + 0][a_rm] = av.x;
        As[a_c4 + 1][a_rm] = av.y;
        As[a_c4 + 2][a_rm] = av.z;
        As[a_c4 + 3][a_rm] = av.w;

        float4 bv = *(const float4*)(Bbase + (size_t)(k0 + b_kk) * HID);
        *(float4*)&Bs[b_kk][b_n] = bv;
        __syncthreads();

#pragma unroll
        for (int kk = 0; kk < 8; kk++) {
            float a[8], b[8];
            *(float4*)&a[0] = *(const float4*)&As[kk][ty * 8];
            *(float4*)&a[4] = *(const float4*)&As[kk][ty * 8 + 4];
            *(float4*)&b[0] = *(const float4*)&Bs[kk][tx * 8];
            *(float4*)&b[4] = *(const float4*)&Bs[kk][tx * 8 + 4];
#pragma unroll
            for (int i = 0; i < 8; i++)
#pragma unroll
                for (int j = 0; j < 8; j++) acc[i][j] += a[i] * b[j];
        }
        __syncthreads();
    }

    // epilogue: bias + exact gelu, write H
    const float* b1p = b1 + e * HID + n0 + tx * 8;
#pragma unroll
    for (int i = 0; i < 8; i++) {
        int m = m0 + ty * 8 + i;
        if (m >= Me) continue;
        float* Hrow = g_H + (size_t)(e * CAP + m) * HID + n0 + tx * 8;
#pragma unroll
        for (int j = 0; j < 8; j++) {
            float h = acc[i][j] + b1p[j];
            Hrow[j] = 0.5f * h * (1.f + erff(h * 0.7071067811865476f));
        }
    }
}

// ---------------------------------------------------------------------------
// GEMM2: Y = H @ w2[e] + b2[e]   [Me x 3072] @ [3072 x 768]
// ---------------------------------------------------------------------------
__global__ __launch_bounds__(256) void gemm2_kernel(
    const float* __restrict__ w2,
    const float* __restrict__ b2)
{
    const int e  = blockIdx.z;
    const int Me = min(g_cnt[e], CAP);
    const int m0 = blockIdx.y * 128;
    if (m0 >= Me) return;
    const int n0 = blockIdx.x * 128;

    __shared__ float As[8][128];
    __shared__ float Bs[8][128];

    const int tid  = threadIdx.x;
    const int a_rm = tid >> 1;
    const int a_c4 = (tid & 1) * 4;
    const bool a_ok = (m0 + a_rm < Me);
    const float* Arow = g_H + (size_t)(e * CAP + m0 + a_rm) * HID;

    const int b_kk = tid >> 5;
    const int b_n  = (tid & 31) * 4;
    const float* Bbase = w2 + (size_t)e * HID * DIM + n0 + b_n;

    const int ty = tid >> 4, tx = tid & 15;

    float acc[8][8];
#pragma unroll
    for (int i = 0; i < 8; i++)
#pragma unroll
        for (int j = 0; j < 8; j++) acc[i][j] = 0.f;

    for (int k0 = 0; k0 < HID; k0 += 8) {
        float4 av = make_float4(0.f, 0.f, 0.f, 0.f);
        if (a_ok) av = *(const float4*)(Arow + k0 + a_c4);
        As[a_c4 + 0][a_rm] = av.x;
        As[a_c4 + 1][a_rm] = av.y;
        As[a_c4 + 2][a_rm] = av.z;
        As[a_c4 + 3][a_rm] = av.w;

        float4 bv = *(const float4*)(Bbase + (size_t)(k0 + b_kk) * DIM);
        *(float4*)&Bs[b_kk][b_n] = bv;
        __syncthreads();

#pragma unroll
        for (int kk = 0; kk < 8; kk++) {
            float a[8], b[8];
            *(float4*)&a[0] = *(const float4*)&As[kk][ty * 8];
            *(float4*)&a[4] = *(const float4*)&As[kk][ty * 8 + 4];
            *(float4*)&b[0] = *(const float4*)&Bs[kk][tx * 8];
            *(float4*)&b[4] = *(const float4*)&Bs[kk][tx * 8 + 4];
#pragma unroll
            for (int i = 0; i < 8; i++)
#pragma unroll
                for (int j = 0; j < 8; j++) acc[i][j] += a[i] * b[j];
        }
        __syncthreads();
    }

    const float* b2p = b2 + e * DIM + n0 + tx * 8;
#pragma unroll
    for (int i = 0; i < 8; i++) {
        int m = m0 + ty * 8 + i;
        if (m >= Me) continue;
        float* Yrow = g_Y + (size_t)(e * CAP + m) * DIM + n0 + tx * 8;
#pragma unroll
        for (int j = 0; j < 8; j++) Yrow[j] = acc[i][j] + b2p[j];
    }
}

// ---------------------------------------------------------------------------
// Kernel 5: weighted 2-way combine + LayerNorm. One block (256 thr) per token.
// ---------------------------------------------------------------------------
__global__ __launch_bounds__(256) void combine_ln_kernel(
    const float* __restrict__ lnw,
    const float* __restrict__ lnb,
    float* __restrict__ out)
{
    const int t   = blockIdx.x;
    const int tid = threadIdx.x;
    const int s0  = g_slot[2 * t + 0];
    const int s1  = g_slot[2 * t + 1];
    const float w0 = g_route_w[2 * t + 0];
    const float w1 = g_route_w[2 * t + 1];

    float v[3];
    float sum = 0.f;
#pragma unroll
    for (int r = 0; r < 3; r++) {
        int i = r * 256 + tid;
        float a = (s0 >= 0) ? g_Y[(size_t)s0 * DIM + i] : 0.f;
        float b = (s1 >= 0) ? g_Y[(size_t)s1 * DIM + i] : 0.f;
        v[r] = w0 * a + w1 * b;
        sum += v[r];
    }

    __shared__ float red[256];
    red[tid] = sum;
    __syncthreads();
#pragma unroll
    for (int o = 128; o > 0; o >>= 1) {
        if (tid < o) red[tid] += red[tid + o];
        __syncthreads();
    }
    float mu = red[0] * (1.f / (float)DIM);
    __syncthreads();

    float sq = 0.f;
#pragma unroll
    for (int r = 0; r < 3; r++) { float d = v[r] - mu; sq += d * d; }
    red[tid] = sq;
    __syncthreads();
#pragma unroll
    for (int o = 128; o > 0; o >>= 1) {
        if (tid < o) red[tid] += red[tid + o];
        __syncthreads();
    }
    float rstd = rsqrtf(red[0] * (1.f / (float)DIM) + 1e-5f);

#pragma unroll
    for (int r = 0; r < 3; r++) {
        int i = r * 256 + tid;
        out[(size_t)t * DIM + i] = (v[r] - mu) * rstd * lnw[i] + lnb[i];
    }
}

// ---------------------------------------------------------------------------
// Launch
// ---------------------------------------------------------------------------
extern "C" void kernel_launch(void* const* d_in, const int* in_sizes, int n_in,
                              void* d_out, int out_size)
{
    const float* x   = (const float*)d_in[0];
    const float* wg  = (const float*)d_in[1];
    const float* w1  = (const float*)d_in[2];
    const float* b1  = (const float*)d_in[3];
    const float* w2  = (const float*)d_in[4];
    const float* b2  = (const float*)d_in[5];
    const float* lnw = (const float*)d_in[6];
    const float* lnb = (const float*)d_in[7];
    float* out = (float*)d_out;

    zero_counts_kernel<<<1, 32>>>();
    router_kernel<<<N_TOK / 8, 256>>>(x, wg);
    assign_kernel<<<N_TOK / 256, 256>>>();
    gemm1_kernel<<<dim3(HID / 128, (CAP + 127) / 128, NEXP), 256>>>(x, w1, b1);
    gemm2_kernel<<<dim3(DIM / 128, (CAP + 127) / 128, NEXP), 256>>>(w2, b2);
    combine_ln_kernel<<<N_TOK, 256>>>(lnw, lnb, out);
}

// round 3
// speedup vs baseline: 3.3662x; 3.3662x over previous
#include <cuda_runtime.h>
#include <math.h>
#include <stdint.h>

#define N_TOK 32768
#define DIM   768
#define HID   3072
#define NEXP  8
#define CAP   10240

// ---------------------------------------------------------------------------
// Scratch (device globals: allocation-free per harness rules)
// ---------------------------------------------------------------------------
__device__ int   g_cnt[NEXP];
__device__ int   g_route_e[N_TOK * 2];
__device__ float g_route_w[N_TOK * 2];
__device__ int   g_tokidx[NEXP * CAP];
__device__ int   g_slot[N_TOK * 2];
__device__ float g_xg [(size_t)NEXP * CAP * DIM];   // gathered tokens, tf32-rounded
__device__ float g_w1r[(size_t)NEXP * DIM * HID];   // w1 tf32-rounded (same layout)
__device__ float g_w2r[(size_t)NEXP * HID * DIM];   // w2 tf32-rounded
__device__ float g_H  [(size_t)NEXP * CAP * HID];   // gelu output, tf32-rounded
__device__ float g_Y  [(size_t)NEXP * CAP * DIM];   // expert output fp32

// ---------------------------------------------------------------------------
// Helpers
// ---------------------------------------------------------------------------
__device__ __forceinline__ float tf32r(float x) {
    uint32_t u;
    asm("cvt.rna.tf32.f32 %0, %1;" : "=r"(u) : "f"(x));
    return __uint_as_float(u);
}
__device__ __forceinline__ void cp16(void* dst, const float* src) {
    uint32_t d;
    asm("{ .reg .u64 t; cvta.to.shared.u64 t, %1; cvt.u32.u64 %0, t; }" : "=r"(d) : "l"(dst));
    asm volatile("cp.async.cg.shared.global [%0], [%1], 16;" :: "r"(d), "l"(src));
}
#define CP_COMMIT() asm volatile("cp.async.commit_group;" ::: "memory")
#define CP_WAIT1()  asm volatile("cp.async.wait_group 1;" ::: "memory")

#define MMA_TF32(c, a, b) \
    asm volatile("mma.sync.aligned.m16n8k8.row.col.f32.tf32.tf32.f32 " \
        "{%0,%1,%2,%3}, {%4,%5,%6,%7}, {%8,%9}, {%0,%1,%2,%3};" \
        : "+f"((c)[0]), "+f"((c)[1]), "+f"((c)[2]), "+f"((c)[3]) \
        : "r"((a)[0]), "r"((a)[1]), "r"((a)[2]), "r"((a)[3]), \
          "r"((b)[0]), "r"((b)[1]))

// ---------------------------------------------------------------------------
// Kernel 0: zero the per-expert counters
// ---------------------------------------------------------------------------
__global__ void zero_counts_kernel() {
    if (threadIdx.x < NEXP) g_cnt[threadIdx.x] = 0;
}

// ---------------------------------------------------------------------------
// Kernel 1: router. One warp per token (exact fp32, matches reference top-k)
// ---------------------------------------------------------------------------
__global__ __launch_bounds__(256) void router_kernel(
    const float* __restrict__ x, const float* __restrict__ wg)
{
    int warp = (blockIdx.x * blockDim.x + threadIdx.x) >> 5;
    int lane = threadIdx.x & 31;
    if (warp >= N_TOK) return;
    const float* xr = x + (size_t)warp * DIM;

    float acc[NEXP];
#pragma unroll
    for (int e = 0; e < NEXP; e++) acc[e] = 0.f;
    for (int j = lane; j < DIM; j += 32) {
        float xv = xr[j];
        const float* wr = wg + j * NEXP;
#pragma unroll
        for (int e = 0; e < NEXP; e++) acc[e] += xv * wr[e];
    }
#pragma unroll
    for (int e = 0; e < NEXP; e++) {
#pragma unroll
        for (int o = 16; o > 0; o >>= 1)
            acc[e] += __shfl_xor_sync(0xffffffffu, acc[e], o);
    }
    if (lane == 0) {
        int e0 = 0; float v0 = acc[0];
#pragma unroll
        for (int e = 1; e < NEXP; e++) if (acc[e] > v0) { v0 = acc[e]; e0 = e; }
        int e1 = -1; float v1 = -3.4e38f;
#pragma unroll
        for (int e = 0; e < NEXP; e++) if (e != e0 && acc[e] > v1) { v1 = acc[e]; e1 = e; }
        float ex = expf(v1 - v0);
        float s  = 1.f + ex;
        g_route_e[2 * warp + 0] = e0;  g_route_w[2 * warp + 0] = 1.f / s;
        g_route_e[2 * warp + 1] = e1;  g_route_w[2 * warp + 1] = ex / s;
    }
}

// ---------------------------------------------------------------------------
// Kernel 2: slot assignment
// ---------------------------------------------------------------------------
__global__ void assign_kernel() {
    int t = blockIdx.x * blockDim.x + threadIdx.x;
    if (t >= N_TOK) return;
#pragma unroll
    for (int k = 0; k < 2; k++) {
        int e = g_route_e[2 * t + k];
        int pos = atomicAdd(&g_cnt[e], 1);
        if (pos < CAP) {
            g_tokidx[e * CAP + pos] = t;
            g_slot[2 * t + k] = e * CAP + pos;
        } else {
            g_slot[2 * t + k] = -1;
        }
    }
}

// ---------------------------------------------------------------------------
// Kernel 3: gather routed tokens (tf32-rounded) into contiguous rows
// ---------------------------------------------------------------------------
__global__ __launch_bounds__(192) void gather_kernel(const float* __restrict__ x) {
    int e = blockIdx.y, pos = blockIdx.x;
    int Me = min(g_cnt[e], CAP);
    if (pos >= Me) return;
    int tok = g_tokidx[e * CAP + pos];
    const float4* s = (const float4*)(x + (size_t)tok * DIM);
    float4* d = (float4*)(g_xg + (size_t)(e * CAP + pos) * DIM);
    float4 v = s[threadIdx.x];
    v.x = tf32r(v.x); v.y = tf32r(v.y); v.z = tf32r(v.z); v.w = tf32r(v.w);
    d[threadIdx.x] = v;
}

// ---------------------------------------------------------------------------
// Kernel 4: elementwise tf32 rounding (weights)
// ---------------------------------------------------------------------------
__global__ __launch_bounds__(256) void round_tf32_kernel(
    const float* __restrict__ src, float* __restrict__ dst, int n4)
{
    int i = blockIdx.x * blockDim.x + threadIdx.x;
    if (i >= n4) return;
    float4 v = ((const float4*)src)[i];
    v.x = tf32r(v.x); v.y = tf32r(v.y); v.z = tf32r(v.z); v.w = tf32r(v.w);
    ((float4*)dst)[i] = v;
}

// ---------------------------------------------------------------------------
// tf32 mma.sync GEMM:  C[128 x 128] tile = A[128 x K] @ W[K x N] slice
//   A: [rows][KDIM] K-major (g_xg or g_H). W: [e][KDIM][NDIM] row-major (k,n).
//   Smem A tile [128][36] (pad 4), B tile [32][136] (pad 8): conflict-free
//   fragment loads. Double-buffered cp.async, BK=32 (4 k8 steps).
// ---------------------------------------------------------------------------
template<int KDIM, int NDIM, bool GELU_EPI>
__global__ __launch_bounds__(256, 2) void gemm_tc_kernel(
    const float* __restrict__ A,
    const float* __restrict__ W,
    const float* __restrict__ bias,
    float* __restrict__ Cout)
{
    const int e  = blockIdx.z;
    const int Me = min(g_cnt[e], CAP);
    const int m0 = blockIdx.y * 128;
    if (m0 >= Me) return;
    const int n0 = blockIdx.x * 128;

    extern __shared__ float smem[];
    // offsets in floats: A stages [0,4608), [4608,9216); B [9216,13568), [13568,17920)
    float* sA[2] = { smem,        smem + 4608 };
    float* sB[2] = { smem + 9216, smem + 13568 };

    const int tid  = threadIdx.x;
    const int wid  = tid >> 5;
    const int lid  = tid & 31;
    const int gid  = lid >> 2;
    const int tig  = lid & 3;
    const int warpM = (wid >> 1) * 32;   // 0,32,64,96
    const int warpN = (wid & 1) * 64;    // 0,64

    const float* Ag = A + (size_t)(e * CAP + m0) * KDIM;
    const float* Wg = W + (size_t)e * KDIM * NDIM + n0;
    constexpr int NCH = KDIM / 32;

    float acc[2][8][4];
#pragma unroll
    for (int mf = 0; mf < 2; mf++)
#pragma unroll
        for (int nf = 0; nf < 8; nf++)
#pragma unroll
            for (int q = 0; q < 4; q++) acc[mf][nf][q] = 0.f;

    auto load_chunk = [&](int s, int kc) {
        // A: 128 rows x 32 floats -> 1024 float4, 4 per thread
#pragma unroll
        for (int j = 0; j < 4; j++) {
            int q = j * 256 + tid;
            int r = q >> 3, c4 = q & 7;
            cp16(&sA[s][r * 36 + c4 * 4], Ag + (size_t)r * KDIM + kc + c4 * 4);
        }
        // B: 32 k-rows x 128 floats -> 1024 float4, 4 per thread
#pragma unroll
        for (int j = 0; j < 4; j++) {
            int q = j * 256 + tid;
            int r = q >> 5, c4 = q & 31;
            cp16(&sB[s][r * 136 + c4 * 4], Wg + (size_t)(kc + r) * NDIM + c4 * 4);
        }
    };

    load_chunk(0, 0);
    CP_COMMIT();

    for (int i = 0; i < NCH; i++) {
        if (i + 1 < NCH) load_chunk((i + 1) & 1, (i + 1) * 32);
        CP_COMMIT();
        CP_WAIT1();           // chunk i resident
        __syncthreads();

        const uint32_t* pA = (const uint32_t*)sA[i & 1];
        const uint32_t* pB = (const uint32_t*)sB[i & 1];
#pragma unroll
        for (int ks = 0; ks < 4; ks++) {
            const int k = ks * 8;
            uint32_t a[2][4], b[8][2];
#pragma unroll
            for (int mf = 0; mf < 2; mf++) {
                int base = (warpM + mf * 16 + gid) * 36 + k + tig;
                a[mf][0] = pA[base];
                a[mf][1] = pA[base + 8 * 36];
                a[mf][2] = pA[base + 4];
                a[mf][3] = pA[base + 8 * 36 + 4];
            }
#pragma unroll
            for (int nf = 0; nf < 8; nf++) {
                int base = (k + tig) * 136 + warpN + nf * 8 + gid;
                b[nf][0] = pB[base];
                b[nf][1] = pB[base + 4 * 136];
            }
#pragma unroll
            for (int mf = 0; mf < 2; mf++)
#pragma unroll
                for (int nf = 0; nf < 8; nf++)
                    MMA_TF32(acc[mf][nf], a[mf], b[nf]);
        }
        __syncthreads();      // protect buffer (i+1)&1 before next overwrite
    }

    // epilogue
    const float* bp = bias + (size_t)e * NDIM + n0 + warpN;
#pragma unroll
    for (int mf = 0; mf < 2; mf++) {
#pragma unroll
        for (int half = 0; half < 2; half++) {
            const int m = m0 + warpM + mf * 16 + gid + half * 8;
            if (m >= Me) continue;
            float* Crow = Cout + (size_t)(e * CAP + m) * NDIM + n0 + warpN;
#pragma unroll
            for (int nf = 0; nf < 8; nf++) {
                float v0 = acc[mf][nf][half * 2 + 0] + bp[nf * 8 + tig * 2 + 0];
                float v1 = acc[mf][nf][half * 2 + 1] + bp[nf * 8 + tig * 2 + 1];
                if (GELU_EPI) {
                    v0 = tf32r(0.5f * v0 * (1.f + erff(v0 * 0.70710678118654752f)));
                    v1 = tf32r(0.5f * v1 * (1.f + erff(v1 * 0.70710678118654752f)));
                }
                float2 o; o.x = v0; o.y = v1;
                *(float2*)(Crow + nf * 8 + tig * 2) = o;
            }
        }
    }
}

// ---------------------------------------------------------------------------
// combine + LayerNorm
// ---------------------------------------------------------------------------
__global__ __launch_bounds__(256) void combine_ln_kernel(
    const float* __restrict__ lnw,
    const float* __restrict__ lnb,
    float* __restrict__ out)
{
    const int t   = blockIdx.x;
    const int tid = threadIdx.x;
    const int s0  = g_slot[2 * t + 0];
    const int s1  = g_slot[2 * t + 1];
    const float w0 = g_route_w[2 * t + 0];
    const float w1 = g_route_w[2 * t + 1];

    float v[3];
    float sum = 0.f;
#pragma unroll
    for (int r = 0; r < 3; r++) {
        int i = r * 256 + tid;
        float a = (s0 >= 0) ? g_Y[(size_t)s0 * DIM + i] : 0.f;
        float b = (s1 >= 0) ? g_Y[(size_t)s1 * DIM + i] : 0.f;
        v[r] = w0 * a + w1 * b;
        sum += v[r];
    }

    __shared__ float red[256];
    red[tid] = sum;
    __syncthreads();
#pragma unroll
    for (int o = 128; o > 0; o >>= 1) {
        if (tid < o) red[tid] += red[tid + o];
        __syncthreads();
    }
    float mu = red[0] * (1.f / (float)DIM);
    __syncthreads();

    float sq = 0.f;
#pragma unroll
    for (int r = 0; r < 3; r++) { float d = v[r] - mu; sq += d * d; }
    red[tid] = sq;
    __syncthreads();
#pragma unroll
    for (int o = 128; o > 0; o >>= 1) {
        if (tid < o) red[tid] += red[tid + o];
        __syncthreads();
    }
    float rstd = rsqrtf(red[0] * (1.f / (float)DIM) + 1e-5f);

#pragma unroll
    for (int r = 0; r < 3; r++) {
        int i = r * 256 + tid;
        out[(size_t)t * DIM + i] = (v[r] - mu) * rstd * lnw[i] + lnb[i];
    }
}

// ---------------------------------------------------------------------------
// Launch
// ---------------------------------------------------------------------------
extern "C" void kernel_launch(void* const* d_in, const int* in_sizes, int n_in,
                              void* d_out, int out_size)
{
    const float* x   = (const float*)d_in[0];
    const float* wg  = (const float*)d_in[1];
    const float* w1  = (const float*)d_in[2];
    const float* b1  = (const float*)d_in[3];
    const float* w2  = (const float*)d_in[4];
    const float* b2  = (const float*)d_in[5];
    const float* lnw = (const float*)d_in[6];
    const float* lnb = (const float*)d_in[7];
    float* out = (float*)d_out;

    const int SMEM_BYTES = 17920 * 4;   // 71680
    cudaFuncSetAttribute(gemm_tc_kernel<DIM, HID, true>,
                         cudaFuncAttributeMaxDynamicSharedMemorySize, SMEM_BYTES);
    cudaFuncSetAttribute(gemm_tc_kernel<HID, DIM, false>,
                         cudaFuncAttributeMaxDynamicSharedMemorySize, SMEM_BYTES);

    float* w1r; cudaGetSymbolAddress((void**)&w1r, g_w1r);
    float* w2r; cudaGetSymbolAddress((void**)&w2r, g_w2r);
    float* xg;  cudaGetSymbolAddress((void**)&xg,  g_xg);
    float* Hbuf; cudaGetSymbolAddress((void**)&Hbuf, g_H);
    float* Ybuf; cudaGetSymbolAddress((void**)&Ybuf, g_Y);

    zero_counts_kernel<<<1, 32>>>();
    router_kernel<<<N_TOK / 8, 256>>>(x, wg);
    assign_kernel<<<N_TOK / 256, 256>>>();

    const int W_ELEMS4 = NEXP * DIM * HID / 4;
    round_tf32_kernel<<<(W_ELEMS4 + 255) / 256, 256>>>(w1, w1r, W_ELEMS4);
    round_tf32_kernel<<<(W_ELEMS4 + 255) / 256, 256>>>(w2, w2r, W_ELEMS4);

    gather_kernel<<<dim3(CAP, NEXP), 192>>>(x);

    gemm_tc_kernel<DIM, HID, true><<<dim3(HID / 128, CAP / 128, NEXP), 256, SMEM_BYTES>>>(
        xg, w1r, b1, Hbuf);
    gemm_tc_kernel<HID, DIM, false><<<dim3(DIM / 128, CAP / 128, NEXP), 256, SMEM_BYTES>>>(
        Hbuf, w2r, b2, Ybuf);

    combine_ln_kernel<<<N_TOK, 256>>>(lnw, lnb, out);
}

// round 4
// speedup vs baseline: 3.3704x; 1.0013x over previous
#include <cuda_runtime.h>
#include <math.h>
#include <stdint.h>

#define N_TOK 32768
#define DIM   768
#define HID   3072
#define NEXP  8
#define CAP   10240

// ---------------------------------------------------------------------------
// Scratch (device globals: allocation-free per harness rules)
// ---------------------------------------------------------------------------
__device__ int   g_cnt[NEXP];
__device__ int   g_route_e[N_TOK * 2];
__device__ float g_route_w[N_TOK * 2];
__device__ int   g_tokidx[NEXP * CAP];
__device__ int   g_slot[N_TOK * 2];
__device__ float g_xg [(size_t)NEXP * CAP * DIM];   // gathered tokens, tf32-rounded
__device__ float g_w1r[(size_t)NEXP * DIM * HID];   // w1 tf32-rounded (same layout)
__device__ float g_w2r[(size_t)NEXP * HID * DIM];   // w2 tf32-rounded
__device__ float g_H  [(size_t)NEXP * CAP * HID];   // gelu output, tf32-rounded
__device__ float g_Y  [(size_t)NEXP * CAP * DIM];   // expert output fp32

// ---------------------------------------------------------------------------
// Helpers
// ---------------------------------------------------------------------------
__device__ __forceinline__ float tf32r(float x) {
    uint32_t u;
    asm("cvt.rna.tf32.f32 %0, %1;" : "=r"(u) : "f"(x));
    return __uint_as_float(u);
}
__device__ __forceinline__ void cp16(void* dst, const float* src) {
    uint32_t d;
    asm("{ .reg .u64 t; cvta.to.shared.u64 t, %1; cvt.u32.u64 %0, t; }" : "=r"(d) : "l"(dst));
    asm volatile("cp.async.cg.shared.global [%0], [%1], 16;" :: "r"(d), "l"(src));
}
#define CP_COMMIT() asm volatile("cp.async.commit_group;" ::: "memory")
#define CP_WAIT1()  asm volatile("cp.async.wait_group 1;" ::: "memory")

#define MMA_TF32(c, a, b) \
    asm volatile("mma.sync.aligned.m16n8k8.row.col.f32.tf32.tf32.f32 " \
        "{%0,%1,%2,%3}, {%4,%5,%6,%7}, {%8,%9}, {%0,%1,%2,%3};" \
        : "+f"((c)[0]), "+f"((c)[1]), "+f"((c)[2]), "+f"((c)[3]) \
        : "r"((a)[0]), "r"((a)[1]), "r"((a)[2]), "r"((a)[3]), \
          "r"((b)[0]), "r"((b)[1]))

// ---------------------------------------------------------------------------
// Kernel 0: zero the per-expert counters
// ---------------------------------------------------------------------------
__global__ void zero_counts_kernel() {
    if (threadIdx.x < NEXP) g_cnt[threadIdx.x] = 0;
}

// ---------------------------------------------------------------------------
// Kernel 1: router. One warp per token (exact fp32, matches reference top-k)
// ---------------------------------------------------------------------------
__global__ __launch_bounds__(256) void router_kernel(
    const float* __restrict__ x, const float* __restrict__ wg)
{
    int warp = (blockIdx.x * blockDim.x + threadIdx.x) >> 5;
    int lane = threadIdx.x & 31;
    if (warp >= N_TOK) return;
    const float* xr = x + (size_t)warp * DIM;

    float acc[NEXP];
#pragma unroll
    for (int e = 0; e < NEXP; e++) acc[e] = 0.f;
    for (int j = lane; j < DIM; j += 32) {
        float xv = xr[j];
        const float* wr = wg + j * NEXP;
#pragma unroll
        for (int e = 0; e < NEXP; e++) acc[e] += xv * wr[e];
    }
#pragma unroll
    for (int e = 0; e < NEXP; e++) {
#pragma unroll
        for (int o = 16; o > 0; o >>= 1)
            acc[e] += __shfl_xor_sync(0xffffffffu, acc[e], o);
    }
    if (lane == 0) {
        int e0 = 0; float v0 = acc[0];
#pragma unroll
        for (int e = 1; e < NEXP; e++) if (acc[e] > v0) { v0 = acc[e]; e0 = e; }
        int e1 = -1; float v1 = -3.4e38f;
#pragma unroll
        for (int e = 0; e < NEXP; e++) if (e != e0 && acc[e] > v1) { v1 = acc[e]; e1 = e; }
        float ex = expf(v1 - v0);
        float s  = 1.f + ex;
        g_route_e[2 * warp + 0] = e0;  g_route_w[2 * warp + 0] = 1.f / s;
        g_route_e[2 * warp + 1] = e1;  g_route_w[2 * warp + 1] = ex / s;
    }
}

// ---------------------------------------------------------------------------
// Kernel 2: slot assignment
// ---------------------------------------------------------------------------
__global__ void assign_kernel() {
    int t = blockIdx.x * blockDim.x + threadIdx.x;
    if (t >= N_TOK) return;
#pragma unroll
    for (int k = 0; k < 2; k++) {
        int e = g_route_e[2 * t + k];
        int pos = atomicAdd(&g_cnt[e], 1);
        if (pos < CAP) {
            g_tokidx[e * CAP + pos] = t;
            g_slot[2 * t + k] = e * CAP + pos;
        } else {
            g_slot[2 * t + k] = -1;
        }
    }
}

// ---------------------------------------------------------------------------
// Kernel 3: gather routed tokens (tf32-rounded) into contiguous rows
// ---------------------------------------------------------------------------
__global__ __launch_bounds__(192) void gather_kernel(const float* __restrict__ x) {
    int e = blockIdx.y, pos = blockIdx.x;
    int Me = min(g_cnt[e], CAP);
    if (pos >= Me) return;
    int tok = g_tokidx[e * CAP + pos];
    const float4* s = (const float4*)(x + (size_t)tok * DIM);
    float4* d = (float4*)(g_xg + (size_t)(e * CAP + pos) * DIM);
    float4 v = s[threadIdx.x];
    v.x = tf32r(v.x); v.y = tf32r(v.y); v.z = tf32r(v.z); v.w = tf32r(v.w);
    d[threadIdx.x] = v;
}

// ---------------------------------------------------------------------------
// Kernel 4: elementwise tf32 rounding (weights)
// ---------------------------------------------------------------------------
__global__ __launch_bounds__(256) void round_tf32_kernel(
    const float* __restrict__ src, float* __restrict__ dst, int n4)
{
    int i = blockIdx.x * blockDim.x + threadIdx.x;
    if (i >= n4) return;
    float4 v = ((const float4*)src)[i];
    v.x = tf32r(v.x); v.y = tf32r(v.y); v.z = tf32r(v.z); v.w = tf32r(v.w);
    ((float4*)dst)[i] = v;
}

// ---------------------------------------------------------------------------
// tf32 mma.sync GEMM:  C[128 x 128] tile = A[128 x K] @ W[K x N] slice
//   A: [rows][KDIM] K-major (g_xg or g_H). W: [e][KDIM][NDIM] row-major (k,n).
//   Smem A tile [128][36] (pad 4), B tile [32][136] (pad 8): conflict-free
//   fragment loads. Double-buffered cp.async, BK=32 (4 k8 steps).
// ---------------------------------------------------------------------------
template<int KDIM, int NDIM, bool GELU_EPI>
__global__ __launch_bounds__(256, 2) void gemm_tc_kernel(
    const float* __restrict__ A,
    const float* __restrict__ W,
    const float* __restrict__ bias,
    float* __restrict__ Cout)
{
    const int e  = blockIdx.z;
    const int Me = min(g_cnt[e], CAP);
    const int m0 = blockIdx.y * 128;
    if (m0 >= Me) return;
    const int n0 = blockIdx.x * 128;

    extern __shared__ float smem[];
    // offsets in floats: A stages [0,4608), [4608,9216); B [9216,13568), [13568,17920)
    float* sA[2] = { smem,        smem + 4608 };
    float* sB[2] = { smem + 9216, smem + 13568 };

    const int tid  = threadIdx.x;
    const int wid  = tid >> 5;
    const int lid  = tid & 31;
    const int gid  = lid >> 2;
    const int tig  = lid & 3;
    const int warpM = (wid >> 1) * 32;   // 0,32,64,96
    const int warpN = (wid & 1) * 64;    // 0,64

    const float* Ag = A + (size_t)(e * CAP + m0) * KDIM;
    const float* Wg = W + (size_t)e * KDIM * NDIM + n0;
    constexpr int NCH = KDIM / 32;

    float acc[2][8][4];
#pragma unroll
    for (int mf = 0; mf < 2; mf++)
#pragma unroll
        for (int nf = 0; nf < 8; nf++)
#pragma unroll
            for (int q = 0; q < 4; q++) acc[mf][nf][q] = 0.f;

    auto load_chunk = [&](int s, int kc) {
        // A: 128 rows x 32 floats -> 1024 float4, 4 per thread
#pragma unroll
        for (int j = 0; j < 4; j++) {
            int q = j * 256 + tid;
            int r = q >> 3, c4 = q & 7;
            cp16(&sA[s][r * 36 + c4 * 4], Ag + (size_t)r * KDIM + kc + c4 * 4);
        }
        // B: 32 k-rows x 128 floats -> 1024 float4, 4 per thread
#pragma unroll
        for (int j = 0; j < 4; j++) {
            int q = j * 256 + tid;
            int r = q >> 5, c4 = q & 31;
            cp16(&sB[s][r * 136 + c4 * 4], Wg + (size_t)(kc + r) * NDIM + c4 * 4);
        }
    };

    load_chunk(0, 0);
    CP_COMMIT();

    for (int i = 0; i < NCH; i++) {
        if (i + 1 < NCH) load_chunk((i + 1) & 1, (i + 1) * 32);
        CP_COMMIT();
        CP_WAIT1();           // chunk i resident
        __syncthreads();

        const uint32_t* pA = (const uint32_t*)sA[i & 1];
        const uint32_t* pB = (const uint32_t*)sB[i & 1];
#pragma unroll
        for (int ks = 0; ks < 4; ks++) {
            const int k = ks * 8;
            uint32_t a[2][4], b[8][2];
#pragma unroll
            for (int mf = 0; mf < 2; mf++) {
                int base = (warpM + mf * 16 + gid) * 36 + k + tig;
                a[mf][0] = pA[base];
                a[mf][1] = pA[base + 8 * 36];
                a[mf][2] = pA[base + 4];
                a[mf][3] = pA[base + 8 * 36 + 4];
            }
#pragma unroll
            for (int nf = 0; nf < 8; nf++) {
                int base = (k + tig) * 136 + warpN + nf * 8 + gid;
                b[nf][0] = pB[base];
                b[nf][1] = pB[base + 4 * 136];
            }
#pragma unroll
            for (int mf = 0; mf < 2; mf++)
#pragma unroll
                for (int nf = 0; nf < 8; nf++)
                    MMA_TF32(acc[mf][nf], a[mf], b[nf]);
        }
        __syncthreads();      // protect buffer (i+1)&1 before next overwrite
    }

    // epilogue
    const float* bp = bias + (size_t)e * NDIM + n0 + warpN;
#pragma unroll
    for (int mf = 0; mf < 2; mf++) {
#pragma unroll
        for (int half = 0; half < 2; half++) {
            const int m = m0 + warpM + mf * 16 + gid + half * 8;
            if (m >= Me) continue;
            float* Crow = Cout + (size_t)(e * CAP + m) * NDIM + n0 + warpN;
#pragma unroll
            for (int nf = 0; nf < 8; nf++) {
                float v0 = acc[mf][nf][half * 2 + 0] + bp[nf * 8 + tig * 2 + 0];
                float v1 = acc[mf][nf][half * 2 + 1] + bp[nf * 8 + tig * 2 + 1];
                if (GELU_EPI) {
                    v0 = tf32r(0.5f * v0 * (1.f + erff(v0 * 0.70710678118654752f)));
                    v1 = tf32r(0.5f * v1 * (1.f + erff(v1 * 0.70710678118654752f)));
                }
                float2 o; o.x = v0; o.y = v1;
                *(float2*)(Crow + nf * 8 + tig * 2) = o;
            }
        }
    }
}

// ---------------------------------------------------------------------------
// combine + LayerNorm
// ---------------------------------------------------------------------------
__global__ __launch_bounds__(256) void combine_ln_kernel(
    const float* __restrict__ lnw,
    const float* __restrict__ lnb,
    float* __restrict__ out)
{
    const int t   = blockIdx.x;
    const int tid = threadIdx.x;
    const int s0  = g_slot[2 * t + 0];
    const int s1  = g_slot[2 * t + 1];
    const float w0 = g_route_w[2 * t + 0];
    const float w1 = g_route_w[2 * t + 1];

    float v[3];
    float sum = 0.f;
#pragma unroll
    for (int r = 0; r < 3; r++) {
        int i = r * 256 + tid;
        float a = (s0 >= 0) ? g_Y[(size_t)s0 * DIM + i] : 0.f;
        float b = (s1 >= 0) ? g_Y[(size_t)s1 * DIM + i] : 0.f;
        v[r] = w0 * a + w1 * b;
        sum += v[r];
    }

    __shared__ float red[256];
    red[tid] = sum;
    __syncthreads();
#pragma unroll
    for (int o = 128; o > 0; o >>= 1) {
        if (tid < o) red[tid] += red[tid + o];
        __syncthreads();
    }
    float mu = red[0] * (1.f / (float)DIM);
    __syncthreads();

    float sq = 0.f;
#pragma unroll
    for (int r = 0; r < 3; r++) { float d = v[r] - mu; sq += d * d; }
    red[tid] = sq;
    __syncthreads();
#pragma unroll
    for (int o = 128; o > 0; o >>= 1) {
        if (tid < o) red[tid] += red[tid + o];
        __syncthreads();
    }
    float rstd = rsqrtf(red[0] * (1.f / (float)DIM) + 1e-5f);

#pragma unroll
    for (int r = 0; r < 3; r++) {
        int i = r * 256 + tid;
        out[(size_t)t * DIM + i] = (v[r] - mu) * rstd * lnw[i] + lnb[i];
    }
}

// ---------------------------------------------------------------------------
// Launch
// ---------------------------------------------------------------------------
extern "C" void kernel_launch(void* const* d_in, const int* in_sizes, int n_in,
                              void* d_out, int out_size)
{
    const float* x   = (const float*)d_in[0];
    const float* wg  = (const float*)d_in[1];
    const float* w1  = (const float*)d_in[2];
    const float* b1  = (const float*)d_in[3];
    const float* w2  = (const float*)d_in[4];
    const float* b2  = (const float*)d_in[5];
    const float* lnw = (const float*)d_in[6];
    const float* lnb = (const float*)d_in[7];
    float* out = (float*)d_out;

    const int SMEM_BYTES = 17920 * 4;   // 71680
    cudaFuncSetAttribute(gemm_tc_kernel<DIM, HID, true>,
                         cudaFuncAttributeMaxDynamicSharedMemorySize, SMEM_BYTES);
    cudaFuncSetAttribute(gemm_tc_kernel<HID, DIM, false>,
                         cudaFuncAttributeMaxDynamicSharedMemorySize, SMEM_BYTES);

    float* w1r; cudaGetSymbolAddress((void**)&w1r, g_w1r);
    float* w2r; cudaGetSymbolAddress((void**)&w2r, g_w2r);
    float* xg;  cudaGetSymbolAddress((void**)&xg,  g_xg);
    float* Hbuf; cudaGetSymbolAddress((void**)&Hbuf, g_H);
    float* Ybuf; cudaGetSymbolAddress((void**)&Ybuf, g_Y);

    zero_counts_kernel<<<1, 32>>>();
    router_kernel<<<N_TOK / 8, 256>>>(x, wg);
    assign_kernel<<<N_TOK / 256, 256>>>();

    const int W_ELEMS4 = NEXP * DIM * HID / 4;
    round_tf32_kernel<<<(W_ELEMS4 + 255) / 256, 256>>>(w1, w1r, W_ELEMS4);
    round_tf32_kernel<<<(W_ELEMS4 + 255) / 256, 256>>>(w2, w2r, W_ELEMS4);

    gather_kernel<<<dim3(CAP, NEXP), 192>>>(x);

    gemm_tc_kernel<DIM, HID, true><<<dim3(HID / 128, CAP / 128, NEXP), 256, SMEM_BYTES>>>(
        xg, w1r, b1, Hbuf);
    gemm_tc_kernel<HID, DIM, false><<<dim3(DIM / 128, CAP / 128, NEXP), 256, SMEM_BYTES>>>(
        Hbuf, w2r, b2, Ybuf);

    combine_ln_kernel<<<N_TOK, 256>>>(lnw, lnb, out);
}

// round 6
// speedup vs baseline: 4.1482x; 1.2308x over previous
#include <cuda_runtime.h>
#include <math.h>
#include <stdint.h>

#define N_TOK 32768
#define DIM   768
#define HID   3072
#define NEXP  8
#define CAP   10240
#define MTILES (CAP / 128)          // 80
#define KCH1  (DIM / 32)            // 24  (GEMM1 k-chunks)
#define KCH2  (HID / 32)            // 96  (GEMM2 k-chunks)

// ---------------------------------------------------------------------------
// Scratch (device globals)
// Fragment-blob layout: a 16KB blob = [sub(8 or {ks,p})][t(32)][j(4)] float units
//   A-blob (128m x 32k):  unit q = (m16blk*4 + ks)*32 + t, j: row+=8*(j&1), col+=4*(j>>1)
//   B-blob (32k x 128n):  unit q = (ks*8 + p)*32 + t,     j: k+=4*(j&1),  n+=8*(j>>1)
// ---------------------------------------------------------------------------
__device__ int   g_cnt[NEXP];
__device__ int   g_route_e[N_TOK * 2];
__device__ float g_route_w[N_TOK * 2];
__device__ int   g_tokidx[NEXP * CAP];
__device__ int   g_slot[N_TOK * 2];
__device__ float g_xg [(size_t)NEXP * MTILES * KCH1 * 4096];    // A blobs GEMM1
__device__ float g_w1f[(size_t)NEXP * (HID/128) * KCH1 * 4096]; // B blobs GEMM1
__device__ float g_w2f[(size_t)NEXP * (DIM/128) * KCH2 * 4096]; // B blobs GEMM2
__device__ float g_H  [(size_t)NEXP * MTILES * KCH2 * 4096];    // A blobs GEMM2
__device__ float g_Y  [(size_t)NEXP * CAP * DIM];               // row-major expert out

// ---------------------------------------------------------------------------
// Helpers
// ---------------------------------------------------------------------------
__device__ __forceinline__ float tf32r(float x) {
    uint32_t u;
    asm("cvt.rna.tf32.f32 %0, %1;" : "=r"(u) : "f"(x));
    return __uint_as_float(u);
}
__device__ __forceinline__ void cp16(void* dst, const float* src) {
    uint32_t d;
    asm("{ .reg .u64 t; cvta.to.shared.u64 t, %1; cvt.u32.u64 %0, t; }" : "=r"(d) : "l"(dst));
    asm volatile("cp.async.cg.shared.global [%0], [%1], 16;" :: "r"(d), "l"(src));
}
#define CP_COMMIT() asm volatile("cp.async.commit_group;" ::: "memory")
#define CP_WAIT1()  asm volatile("cp.async.wait_group 1;" ::: "memory")

#define MMA_TF32(c, a, b) \
    asm volatile("mma.sync.aligned.m16n8k8.row.col.f32.tf32.tf32.f32 " \
        "{%0,%1,%2,%3}, {%4,%5,%6,%7}, {%8,%9}, {%0,%1,%2,%3};" \
        : "+f"((c)[0]), "+f"((c)[1]), "+f"((c)[2]), "+f"((c)[3]) \
        : "r"((a)[0]), "r"((a)[1]), "r"((a)[2]), "r"((a)[3]), \
          "r"((b)[0]), "r"((b)[1]))

// ---------------------------------------------------------------------------
// Kernel 0: zero counters
// ---------------------------------------------------------------------------
__global__ void zero_counts_kernel() {
    if (threadIdx.x < NEXP) g_cnt[threadIdx.x] = 0;
}

// ---------------------------------------------------------------------------
// Kernel 1: router (one warp per token, exact fp32)
// ---------------------------------------------------------------------------
__global__ __launch_bounds__(256) void router_kernel(
    const float* __restrict__ x, const float* __restrict__ wg)
{
    int warp = (blockIdx.x * blockDim.x + threadIdx.x) >> 5;
    int lane = threadIdx.x & 31;
    if (warp >= N_TOK) return;
    const float* xr = x + (size_t)warp * DIM;

    float acc[NEXP];
#pragma unroll
    for (int e = 0; e < NEXP; e++) acc[e] = 0.f;
    for (int j = lane; j < DIM; j += 32) {
        float xv = xr[j];
        const float* wr = wg + j * NEXP;
#pragma unroll
        for (int e = 0; e < NEXP; e++) acc[e] += xv * wr[e];
    }
#pragma unroll
    for (int e = 0; e < NEXP; e++) {
#pragma unroll
        for (int o = 16; o > 0; o >>= 1)
            acc[e] += __shfl_xor_sync(0xffffffffu, acc[e], o);
    }
    if (lane == 0) {
        int e0 = 0; float v0 = acc[0];
#pragma unroll
        for (int e = 1; e < NEXP; e++) if (acc[e] > v0) { v0 = acc[e]; e0 = e; }
        int e1 = -1; float v1 = -3.4e38f;
#pragma unroll
        for (int e = 0; e < NEXP; e++) if (e != e0 && acc[e] > v1) { v1 = acc[e]; e1 = e; }
        float ex = expf(v1 - v0);
        float s  = 1.f + ex;
        g_route_e[2 * warp + 0] = e0;  g_route_w[2 * warp + 0] = 1.f / s;
        g_route_e[2 * warp + 1] = e1;  g_route_w[2 * warp + 1] = ex / s;
    }
}

// ---------------------------------------------------------------------------
// Kernel 2: slot assignment
// ---------------------------------------------------------------------------
__global__ void assign_kernel() {
    int t = blockIdx.x * blockDim.x + threadIdx.x;
    if (t >= N_TOK) return;
#pragma unroll
    for (int k = 0; k < 2; k++) {
        int e = g_route_e[2 * t + k];
        int pos = atomicAdd(&g_cnt[e], 1);
        if (pos < CAP) {
            g_tokidx[e * CAP + pos] = t;
            g_slot[2 * t + k] = e * CAP + pos;
        } else {
            g_slot[2 * t + k] = -1;
        }
    }
}

// ---------------------------------------------------------------------------
// Kernel 3: weight -> B-blob transform + tf32 round.
// ---------------------------------------------------------------------------
__global__ __launch_bounds__(128) void wtransform_kernel(
    const float* __restrict__ w, float* __restrict__ out, int KD, int ND)
{
    const int nkc = KD / 32;
    const int e  = blockIdx.y;
    const int nt = blockIdx.x / nkc;
    const int kc = blockIdx.x % nkc;
    __shared__ float tile[32][132];

    const int tid = threadIdx.x;
    const float* src = w + ((size_t)e * KD + kc * 32) * ND + nt * 128;
#pragma unroll
    for (int u = tid; u < 1024; u += 128) {
        int r = u >> 5, c = (u & 31) * 4;
        float4 v = *(const float4*)(src + (size_t)r * ND + c);
        tile[r][c + 0] = tf32r(v.x);
        tile[r][c + 1] = tf32r(v.y);
        tile[r][c + 2] = tf32r(v.z);
        tile[r][c + 3] = tf32r(v.w);
    }
    __syncthreads();

    float4* dst = (float4*)(out + ((size_t)(e * (ND / 128) + nt) * nkc + kc) * 4096);
#pragma unroll
    for (int u = tid; u < 1024; u += 128) {
        int t = u & 31, p = (u >> 5) & 7, ks = u >> 8;
        int gid = t >> 2, tig = t & 3;
        float4 v;
        v.x = tile[ks * 8 + tig    ][p * 16 + gid];
        v.y = tile[ks * 8 + tig + 4][p * 16 + gid];
        v.z = tile[ks * 8 + tig    ][p * 16 + 8 + gid];
        v.w = tile[ks * 8 + tig + 4][p * 16 + 8 + gid];
        dst[u] = v;
    }
}

// ---------------------------------------------------------------------------
// Kernel 4: gather routed tokens into A-blobs (tf32-rounded).
// ---------------------------------------------------------------------------
__global__ __launch_bounds__(256) void gather_frag_kernel(const float* __restrict__ x) {
    const int e = blockIdx.y;
    const int Me = min(g_cnt[e], CAP);
    const int g16 = blockIdx.x;
    const int base = g16 * 16;
    if (base >= Me) return;

    __shared__ float rows[16][772];
    const int tid = threadIdx.x;

    for (int u = tid; u < 16 * 192; u += 256) {
        int r = u / 192, c = (u % 192) * 4;
        int pos = base + r;
        if (pos < Me) {
            int tok = g_tokidx[e * CAP + pos];
            float4 v = *(const float4*)(x + (size_t)tok * DIM + c);
            rows[r][c + 0] = tf32r(v.x);
            rows[r][c + 1] = tf32r(v.y);
            rows[r][c + 2] = tf32r(v.z);
            rows[r][c + 3] = tf32r(v.w);
        } else {
            rows[r][c + 0] = 0.f; rows[r][c + 1] = 0.f;
            rows[r][c + 2] = 0.f; rows[r][c + 3] = 0.f;
        }
    }
    __syncthreads();

    const int mtile = g16 >> 3, m16blk = g16 & 7;
    float4* outb = (float4*)g_xg;
    for (int u = tid; u < 16 * 192; u += 256) {
        int kc = u >> 7, w = u & 127, t = w & 31;
        int ks = (w >> 5) & 3;
        int gid = t >> 2, tig = t & 3;
        int col = kc * 32 + ks * 8 + tig;
        float4 v;
        v.x = rows[gid    ][col];
        v.y = rows[gid + 8][col];
        v.z = rows[gid    ][col + 4];
        v.w = rows[gid + 8][col + 4];
        outb[((size_t)((e * MTILES + mtile) * KCH1 + kc)) * 1024 + m16blk * 128 + w] = v;
    }
}

// ---------------------------------------------------------------------------
// Fragment-major tf32 GEMM. CTA 128x128, 8 warps (4x2), warp tile 32x64.
//   Mainloop: 6 LDS.128 + 16 mma per warp-ks. 3-stage cp.async pipeline.
// ---------------------------------------------------------------------------
template<int NKCH, int NDIM, bool EPI_FRAG>
__global__ __launch_bounds__(256, 2) void gemm_frag_kernel(
    const float* __restrict__ Ablobs,
    const float* __restrict__ Bblobs,
    const float* __restrict__ bias,
    float* __restrict__ Cout)
{
    const int e  = blockIdx.z;
    const int Me = min(g_cnt[e], CAP);
    const int m0 = blockIdx.y * 128;
    if (m0 >= Me) return;
    const int bx = blockIdx.x;

    extern __shared__ float smem[];           // 3 stages x 32KB
    const int tid = threadIdx.x;
    const int wid = tid >> 5, lid = tid & 31;
    const int gid = lid >> 2, tig = lid & 3;
    const int wMblk = (wid >> 1) * 2;         // m16 block base (0,2,4,6)
    const int pbase = (wid & 1) * 4;          // B pair base (0 or 4)

    const float* Ab = Ablobs + ((size_t)(e * MTILES + blockIdx.y) * NKCH) * 4096;
    const float* Bb = Bblobs + ((size_t)(e * (NDIM / 128) + bx) * NKCH) * 4096;

    float acc[2][8][4];
#pragma unroll
    for (int mf = 0; mf < 2; mf++)
#pragma unroll
        for (int nf = 0; nf < 8; nf++)
#pragma unroll
            for (int q = 0; q < 4; q++) acc[mf][nf][q] = 0.f;

    auto issue = [&](int i) {
        float* dst = smem + (i % 3) * 8192;
        const float* a = Ab + (size_t)i * 4096;
        const float* b = Bb + (size_t)i * 4096;
#pragma unroll
        for (int j = 0; j < 4; j++)
            cp16(dst + (j * 256 + tid) * 4, a + (j * 256 + tid) * 4);
#pragma unroll
        for (int j = 0; j < 4; j++)
            cp16(dst + 4096 + (j * 256 + tid) * 4, b + (j * 256 + tid) * 4);
        CP_COMMIT();
    };

    issue(0);
    issue(1);

    for (int i = 0; i < NKCH; i++) {
        CP_WAIT1();                 // chunk i resident
        __syncthreads();            // + all warps done with chunk i-1's buffer
        if (i + 2 < NKCH) issue(i + 2); else CP_COMMIT();

        const float4* pA = (const float4*)(smem + (i % 3) * 8192);
        const float4* pB = pA + 1024;
#pragma unroll
        for (int ks = 0; ks < 4; ks++) {
            uint32_t a[2][4], b[8][2];
#pragma unroll
            for (int mf = 0; mf < 2; mf++) {
                float4 v = pA[((wMblk + mf) * 4 + ks) * 32 + lid];
                a[mf][0] = __float_as_uint(v.x);
                a[mf][1] = __float_as_uint(v.y);
                a[mf][2] = __float_as_uint(v.z);
                a[mf][3] = __float_as_uint(v.w);
            }
#pragma unroll
            for (int q = 0; q < 4; q++) {
                float4 v = pB[(ks * 8 + pbase + q) * 32 + lid];
                b[2 * q + 0][0] = __float_as_uint(v.x);
                b[2 * q + 0][1] = __float_as_uint(v.y);
                b[2 * q + 1][0] = __float_as_uint(v.z);
                b[2 * q + 1][1] = __float_as_uint(v.w);
            }
#pragma unroll
            for (int mf = 0; mf < 2; mf++)
#pragma unroll
                for (int nf = 0; nf < 8; nf++)
                    MMA_TF32(acc[mf][nf], a[mf], b[nf]);
        }
    }

    const int warpM = (wid >> 1) * 32;
    const int warpN = (wid & 1) * 64;
    const int n0 = bx * 128;
    const float* bp = bias + (size_t)e * NDIM + n0 + warpN;

    if (EPI_FRAG) {
        __syncthreads();            // mainloop fully done before reusing smem
        // stage 4 kchunk H-blobs (64KB) in smem, bank-swizzled on t
#pragma unroll
        for (int mf = 0; mf < 2; mf++)
#pragma unroll
            for (int half = 0; half < 2; half++) {
                int m_local = warpM + mf * 16 + gid + half * 8;
                int mm = m_local & 15, m16blk = m_local >> 4;
#pragma unroll
                for (int nf = 0; nf < 8; nf++)
#pragma unroll
                    for (int c = 0; c < 2; c++) {
                        int n_local = warpN + nf * 8 + tig * 2 + c;
                        float v = acc[mf][nf][half * 2 + c] + bp[nf * 8 + tig * 2 + c];
                        v = tf32r(0.5f * v * (1.f + erff(v * 0.70710678118654752f)));
                        int kc = n_local >> 5, ks = (n_local >> 3) & 3;
                        int t = (mm & 7) * 4 + (n_local & 3);
                        int j = ((n_local >> 2) & 1) * 2 + (mm >> 3);
                        int tw = t ^ (((t >> 3) & 3) << 1);
                        smem[(kc * 1024 + (m16blk * 4 + ks) * 32 + tw) * 4 + j] = v;
                    }
            }
        __syncthreads();
        // linear copy out: 4 consecutive H blobs = 4096 float4 units
        float4* dst = (float4*)(Cout + ((size_t)((e * MTILES + blockIdx.y) * KCH2 + bx * 4)) * 4096);
        const float4* st = (const float4*)smem;
#pragma unroll
        for (int u = tid; u < 4096; u += 256) {
            int t = u & 31;
            int tw = t ^ (((t >> 3) & 3) << 1);
            dst[u] = st[(u & ~31) | tw];
        }
    } else {
#pragma unroll
        for (int mf = 0; mf < 2; mf++)
#pragma unroll
            for (int half = 0; half < 2; half++) {
                int m = m0 + warpM + mf * 16 + gid + half * 8;
                if (m >= Me) continue;
                float* Crow = Cout + (size_t)(e * CAP + m) * NDIM + n0 + warpN;
#pragma unroll
                for (int nf = 0; nf < 8; nf++) {
                    float2 o;
                    o.x = acc[mf][nf][half * 2 + 0] + bp[nf * 8 + tig * 2 + 0];
                    o.y = acc[mf][nf][half * 2 + 1] + bp[nf * 8 + tig * 2 + 1];
                    *(float2*)(Crow + nf * 8 + tig * 2) = o;
                }
            }
    }
}

// ---------------------------------------------------------------------------
// combine + LayerNorm
// ---------------------------------------------------------------------------
__global__ __launch_bounds__(256) void combine_ln_kernel(
    const float* __restrict__ lnw,
    const float* __restrict__ lnb,
    float* __restrict__ out)
{
    const int t   = blockIdx.x;
    const int tid = threadIdx.x;
    const int s0  = g_slot[2 * t + 0];
    const int s1  = g_slot[2 * t + 1];
    const float w0 = g_route_w[2 * t + 0];
    const float w1 = g_route_w[2 * t + 1];

    float v[3];
    float sum = 0.f;
#pragma unroll
    for (int r = 0; r < 3; r++) {
        int i = r * 256 + tid;
        float a = (s0 >= 0) ? g_Y[(size_t)s0 * DIM + i] : 0.f;
        float b = (s1 >= 0) ? g_Y[(size_t)s1 * DIM + i] : 0.f;
        v[r] = w0 * a + w1 * b;
        sum += v[r];
    }

    __shared__ float red[256];
    red[tid] = sum;
    __syncthreads();
#pragma unroll
    for (int o = 128; o > 0; o >>= 1) {
        if (tid < o) red[tid] += red[tid + o];
        __syncthreads();
    }
    float mu = red[0] * (1.f / (float)DIM);
    __syncthreads();

    float sq = 0.f;
#pragma unroll
    for (int r = 0; r < 3; r++) { float d = v[r] - mu; sq += d * d; }
    red[tid] = sq;
    __syncthreads();
#pragma unroll
    for (int o = 128; o > 0; o >>= 1) {
        if (tid < o) red[tid] += red[tid + o];
        __syncthreads();
    }
    float rstd = rsqrtf(red[0] * (1.f / (float)DIM) + 1e-5f);

#pragma unroll
    for (int r = 0; r < 3; r++) {
        int i = r * 256 + tid;
        out[(size_t)t * DIM + i] = (v[r] - mu) * rstd * lnw[i] + lnb[i];
    }
}

// ---------------------------------------------------------------------------
// Launch
// ---------------------------------------------------------------------------
extern "C" void kernel_launch(void* const* d_in, const int* in_sizes, int n_in,
                              void* d_out, int out_size)
{
    const float* x   = (const float*)d_in[0];
    const float* wg  = (const float*)d_in[1];
    const float* w1  = (const float*)d_in[2];
    const float* b1  = (const float*)d_in[3];
    const float* w2  = (const float*)d_in[4];
    const float* b2  = (const float*)d_in[5];
    const float* lnw = (const float*)d_in[6];
    const float* lnb = (const float*)d_in[7];
    float* out = (float*)d_out;

    const int SMEM_BYTES = 98304;
    cudaFuncSetAttribute(gemm_frag_kernel<KCH1, HID, true>,
                         cudaFuncAttributeMaxDynamicSharedMemorySize, SMEM_BYTES);
    cudaFuncSetAttribute(gemm_frag_kernel<KCH2, DIM, false>,
                         cudaFuncAttributeMaxDynamicSharedMemorySize, SMEM_BYTES);

    float* w1f; cudaGetSymbolAddress((void**)&w1f, g_w1f);
    float* w2f; cudaGetSymbolAddress((void**)&w2f, g_w2f);
    float* xg;  cudaGetSymbolAddress((void**)&xg,  g_xg);
    float* Hbuf; cudaGetSymbolAddress((void**)&Hbuf, g_H);
    float* Ybuf; cudaGetSymbolAddress((void**)&Ybuf, g_Y);

    zero_counts_kernel<<<1, 32>>>();
    router_kernel<<<N_TOK / 8, 256>>>(x, wg);
    assign_kernel<<<N_TOK / 256, 256>>>();

    wtransform_kernel<<<dim3((HID / 128) * KCH1, NEXP), 128>>>(w1, w1f, DIM, HID);
    wtransform_kernel<<<dim3((DIM / 128) * KCH2, NEXP), 128>>>(w2, w2f, HID, DIM);

    gather_frag_kernel<<<dim3(CAP / 16, NEXP), 256>>>(x);

    gemm_frag_kernel<KCH1, HID, true><<<dim3(HID / 128, MTILES, NEXP), 256, SMEM_BYTES>>>(
        xg, w1f, b1, Hbuf);
    gemm_frag_kernel<KCH2, DIM, false><<<dim3(DIM / 128, MTILES, NEXP), 256, SMEM_BYTES>>>(
        Hbuf, w2f, b2, Ybuf);

    combine_ln_kernel<<<N_TOK, 256>>>(lnw, lnb, out);
}